// round 4
// baseline (speedup 1.0000x reference)
#include <cuda_runtime.h>
#include <cstdint>

#define Bq 256
#define Tq 64
#define Nq 128
#define Hq 512
#define Kq 640   // Nq + Hq
#define Gq 2048  // 4*Hq

// ---------------- device scratch (no allocs allowed) ----------------
__device__ __align__(16) float g_z2[Bq * Nq * Tq];   // (B,N,T) loop-invariant attention term
__device__ __align__(16) float g_Wt[Gq * Kq];        // W transposed [j'][k], tf32-rounded, j'=h*4+g
__device__ __align__(16) float g_bias[Gq];           // (b_ih+b_hh), j' order
__device__ __align__(16) float g_A[Bq * Kq];         // activation rows: [wx(128) | h(512)] fp32
__device__ __align__(16) float g_C[Bq * Hq];         // cell state
__device__ __align__(16) float g_Z1[Bq * Tq];        // per-step z1

__device__ __forceinline__ float tanh_approx(float x) {
    float y;
    asm("tanh.approx.f32 %0, %1;" : "=f"(y) : "f"(x));
    return y;
}
__device__ __forceinline__ uint32_t tf32r(float f) {
    uint32_t u;
    asm("cvt.rna.tf32.f32 %0, %1;" : "=r"(u) : "f"(f));
    return u;
}

// ---------------- prep: transposed tf32 weights, bias, zero state ----------------
__global__ __launch_bounds__(256) void prep_weights(const float* __restrict__ Wih,
                                                    const float* __restrict__ Whh,
                                                    const float* __restrict__ bih,
                                                    const float* __restrict__ bhh) {
    int i = blockIdx.x * blockDim.x + threadIdx.x;
    int stride = gridDim.x * blockDim.x;
    for (int idx = i; idx < Gq * Kq; idx += stride) {
        int jp = idx / Kq, k = idx - jp * Kq;
        int h = jp >> 2, g = jp & 3;
        int j = g * Hq + h;  // torch gate order i,f,g,o
        float v = (k < Nq) ? Wih[j * Nq + k] : Whh[j * Hq + (k - Nq)];
        g_Wt[idx] = __uint_as_float(tf32r(v));
    }
    for (int idx = i; idx < Gq; idx += stride) {
        int h = idx >> 2, g = idx & 3;
        int j = g * Hq + h;
        g_bias[idx] = bih[j] + bhh[j];
    }
    for (int idx = i; idx < Bq * Kq; idx += stride) g_A[idx] = 0.f;
    for (int idx = i; idx < Bq * Hq; idx += stride) g_C[idx] = 0.f;
}

// ---------------- prep: z2[b,n,s] = sum_t dx[b,t,n]*W_a2[s,t] + b_a2[s] ----------------
__global__ __launch_bounds__(256) void prep_z2(const float* __restrict__ dx,
                                               const float* __restrict__ Wa2,
                                               const float* __restrict__ ba2) {
    __shared__ float sdx[Tq * Nq];  // [t][n], 32KB
    int b = blockIdx.x, tid = threadIdx.x;
    const float* dxb = dx + b * Tq * Nq;
    for (int i = tid; i < Tq * Nq; i += 256) sdx[i] = dxb[i];
    __syncthreads();
    for (int o = tid; o < Nq * Tq; o += 256) {
        int s = o & 63, n = o >> 6;
        float acc = 0.f;
#pragma unroll 8
        for (int t = 0; t < Tq; t++) acc += sdx[t * Nq + n] * __ldg(&Wa2[s * Tq + t]);
        g_z2[(b * Nq + n) * Tq + s] = acc + ba2[s];
    }
}

// ---------------- per step: z1 = [h|c] @ Wa1^T (256x64), 32 blocks x 8 batches ----------------
__global__ __launch_bounds__(256) void step_z1(const float* __restrict__ Wa1,
                                               const float* __restrict__ ba1) {
    __shared__ float hs[8][1024];  // 32KB
    const int tid = threadIdx.x;
    const int b0 = blockIdx.x * 8;
    for (int i = tid; i < 8 * 512; i += 256) {
        int bb = i >> 9, k = i & 511;
        hs[bb][k] = g_A[(b0 + bb) * Kq + Nq + k];
    }
    for (int i = tid; i < 8 * 512; i += 256) {
        int bb = i >> 9, k = i & 511;
        hs[bb][512 + k] = g_C[(b0 + bb) * Hq + k];
    }
    __syncthreads();
    const int s = tid & 63, bg = tid >> 6;  // bg 0..3 -> batches bg*2, bg*2+1
    const float* wr = Wa1 + s * 1024;
    const float* h0 = hs[bg * 2];
    const float* h1 = hs[bg * 2 + 1];
    float acc0 = 0.f, acc1 = 0.f;
#pragma unroll 8
    for (int k = 0; k < 1024; k += 4) {
        float4 w = *(const float4*)(wr + k);
        acc0 += h0[k] * w.x + h0[k + 1] * w.y + h0[k + 2] * w.z + h0[k + 3] * w.w;
        acc1 += h1[k] * w.x + h1[k + 1] * w.y + h1[k + 2] * w.z + h1[k + 3] * w.w;
    }
    float bb = ba1[s];
    g_Z1[(b0 + bg * 2) * Tq + s] = acc0 + bb;
    g_Z1[(b0 + bg * 2 + 1) * Tq + s] = acc1 + bb;
}

// ---------------- per step: e -> softmax over N -> wx ----------------
__global__ __launch_bounds__(128) void step_attn(const float* __restrict__ Wa3,
                                                 const float* __restrict__ ba3,
                                                 const float* __restrict__ dx, int t) {
    __shared__ float z1s[Tq], wa3s[Tq], red[4];
    const int b = blockIdx.x, tid = threadIdx.x;  // tid == n
    if (tid < Tq) {
        z1s[tid] = g_Z1[b * Tq + tid];
        wa3s[tid] = Wa3[tid];
    }
    __syncthreads();
    const float4* z2r = (const float4*)(g_z2 + (b * Nq + tid) * Tq);
    float e = ba3[0];
#pragma unroll
    for (int s4 = 0; s4 < Tq / 4; s4++) {
        float4 z = z2r[s4];
        int s = s4 * 4;
        e += tanh_approx(z1s[s + 0] + z.x) * wa3s[s + 0];
        e += tanh_approx(z1s[s + 1] + z.y) * wa3s[s + 1];
        e += tanh_approx(z1s[s + 2] + z.z) * wa3s[s + 2];
        e += tanh_approx(z1s[s + 3] + z.w) * wa3s[s + 3];
    }
    float m = e;
    for (int o = 16; o > 0; o >>= 1) m = fmaxf(m, __shfl_xor_sync(0xffffffff, m, o));
    if ((tid & 31) == 0) red[tid >> 5] = m;
    __syncthreads();
    m = fmaxf(fmaxf(red[0], red[1]), fmaxf(red[2], red[3]));
    float p = __expf(e - m);
    float sum = p;
    for (int o = 16; o > 0; o >>= 1) sum += __shfl_xor_sync(0xffffffff, sum, o);
    __syncthreads();
    if ((tid & 31) == 0) red[tid >> 5] = sum;
    __syncthreads();
    sum = red[0] + red[1] + red[2] + red[3];
    float w = p / sum;
    float x = dx[(b * Tq + t) * Nq + tid];
    g_A[b * Kq + tid] = w * x;
}

// ---------------- per step: tf32 tensor-core GEMM + fused LSTM ----------------
// CTA tile 32 batches x 64 gate-cols, 8 warps (2m x 4n), warp tile 16x16 (m16n8k8 x2n).
// grid (8, 32) = 256 CTAs.
__global__ __launch_bounds__(256) void step_gemm(float* __restrict__ out, int t) {
    __shared__ float sA[32 * 36];  // [batch][k], pad 36
    __shared__ float sW[64 * 36];  // [j'][k],   pad 36
    __shared__ float sO[32 * 65];  // epilogue staging
    const int tid = threadIdx.x;
    const int bm = blockIdx.x * 32;
    const int jb = blockIdx.y * 64;
    const int wid = tid >> 5, lane = tid & 31;
    const int wm = (wid >> 2) * 16, wn = (wid & 3) * 16;
    const int gid = lane >> 2, tig = lane & 3;

    float c[2][4] = {};

    const int arow = tid >> 3, ak4 = tid & 7;
    const float* Ap = g_A + (bm + arow) * Kq + ak4 * 4;

    float4 ra = *(const float4*)(Ap);
    float4 rw[2];
#pragma unroll
    for (int l = 0; l < 2; l++) {
        int idx = tid + l * 256;
        int r = idx >> 3, k4 = idx & 7;
        rw[l] = *(const float4*)(g_Wt + (jb + r) * Kq + k4 * 4);
    }

    const int NCH = Kq / 32;  // 20
    for (int ch = 0; ch < NCH; ch++) {
        {
            uint32_t* s = (uint32_t*)(sA + arow * 36 + ak4 * 4);
            s[0] = tf32r(ra.x);
            s[1] = tf32r(ra.y);
            s[2] = tf32r(ra.z);
            s[3] = tf32r(ra.w);
        }
#pragma unroll
        for (int l = 0; l < 2; l++) {
            int idx = tid + l * 256;
            int r = idx >> 3, k4 = idx & 7;
            *(float4*)(sW + r * 36 + k4 * 4) = rw[l];
        }
        __syncthreads();
        if (ch + 1 < NCH) {
            int k0 = (ch + 1) * 32;
            ra = *(const float4*)(Ap + k0);
#pragma unroll
            for (int l = 0; l < 2; l++) {
                int idx = tid + l * 256;
                int r = idx >> 3, k4 = idx & 7;
                rw[l] = *(const float4*)(g_Wt + (jb + r) * Kq + k0 + k4 * 4);
            }
        }
        const uint32_t* sAu = (const uint32_t*)sA;
        const uint32_t* sWu = (const uint32_t*)sW;
#pragma unroll
        for (int k8 = 0; k8 < 4; k8++) {
            int cb = k8 * 8 + tig;
            uint32_t a0 = sAu[(wm + gid) * 36 + cb];
            uint32_t a1 = sAu[(wm + gid + 8) * 36 + cb];
            uint32_t a2 = sAu[(wm + gid) * 36 + cb + 4];
            uint32_t a3 = sAu[(wm + gid + 8) * 36 + cb + 4];
#pragma unroll
            for (int nt = 0; nt < 2; nt++) {
                int n = wn + nt * 8 + gid;
                uint32_t b0 = sWu[n * 36 + cb];
                uint32_t b1 = sWu[n * 36 + cb + 4];
                asm volatile(
                    "mma.sync.aligned.m16n8k8.row.col.f32.tf32.tf32.f32 "
                    "{%0,%1,%2,%3},{%4,%5,%6,%7},{%8,%9},{%0,%1,%2,%3};"
                    : "+f"(c[nt][0]), "+f"(c[nt][1]), "+f"(c[nt][2]), "+f"(c[nt][3])
                    : "r"(a0), "r"(a1), "r"(a2), "r"(a3), "r"(b0), "r"(b1));
            }
        }
        __syncthreads();
    }

    // stage C frags to smem
#pragma unroll
    for (int nt = 0; nt < 2; nt++) {
        int col = wn + nt * 8 + 2 * tig;
        sO[(wm + gid) * 65 + col] = c[nt][0];
        sO[(wm + gid) * 65 + col + 1] = c[nt][1];
        sO[(wm + gid + 8) * 65 + col] = c[nt][2];
        sO[(wm + gid + 8) * 65 + col + 1] = c[nt][3];
    }
    __syncthreads();

    // fused LSTM pointwise: 32 batches x 16 h = 512 cells, 2 per thread
#pragma unroll
    for (int u = 0; u < 2; u++) {
        int cell = tid + u * 256;
        int br = cell >> 4, hl = cell & 15;
        int b = bm + br;
        int h = (jb >> 2) + hl;
        float4 bias = *(const float4*)(g_bias + jb + hl * 4);
        float gi = sO[br * 65 + hl * 4 + 0] + bias.x;
        float gf = sO[br * 65 + hl * 4 + 1] + bias.y;
        float gg = sO[br * 65 + hl * 4 + 2] + bias.z;
        float go = sO[br * 65 + hl * 4 + 3] + bias.w;
        float co = g_C[b * Hq + h];
        float si = 1.f / (1.f + __expf(-gi));
        float sf = 1.f / (1.f + __expf(-gf));
        float so = 1.f / (1.f + __expf(-go));
        float cn = sf * co + si * tanhf(gg);
        float hn = so * tanhf(cn);
        g_C[b * Hq + h] = cn;
        g_A[b * Kq + Nq + h] = hn;
        out[(b * Tq + t) * Hq + h] = hn;
    }
}

extern "C" void kernel_launch(void* const* d_in, const int* in_sizes, int n_in,
                              void* d_out, int out_size) {
    const float* dx  = (const float*)d_in[0];
    const float* Wa1 = (const float*)d_in[1];
    const float* ba1 = (const float*)d_in[2];
    const float* Wa2 = (const float*)d_in[3];
    const float* ba2 = (const float*)d_in[4];
    const float* Wa3 = (const float*)d_in[5];
    const float* ba3 = (const float*)d_in[6];
    const float* Wih = (const float*)d_in[7];
    const float* Whh = (const float*)d_in[8];
    const float* bih = (const float*)d_in[9];
    const float* bhh = (const float*)d_in[10];
    float* out = (float*)d_out;

    prep_weights<<<512, 256>>>(Wih, Whh, bih, bhh);
    prep_z2<<<Bq, 256>>>(dx, Wa2, ba2);
    for (int t = 0; t < Tq; t++) {
        step_z1<<<32, 256>>>(Wa1, ba1);
        step_attn<<<Bq, 128>>>(Wa3, ba3, dx, t);
        dim3 g2(8, 32);
        step_gemm<<<g2, 256>>>(out, t);
    }
}

// round 5
// speedup vs baseline: 1.3079x; 1.3079x over previous
#include <cuda_runtime.h>
#include <cstdint>

#define Bq 256
#define Tq 64
#define Nq 128
#define Hq 512
#define Kq 640   // Nq + Hq
#define Gq 2048  // 4*Hq
#define NBLK 128
#define NTHR 256

// ---------------- device scratch (no allocs allowed) ----------------
__device__ __align__(16) float g_z2[Bq * Nq * Tq];   // (B,N,T) attention term
__device__ __align__(16) float g_Wh[Gq * Kq];        // W hi (tf32), [j'][k], j'=h*4+g
__device__ __align__(16) float g_Wl[Gq * Kq];        // W lo (tf32)
__device__ __align__(16) float g_bias[Gq];           // (b_ih+b_hh), j' order
__device__ __align__(16) float g_A[2][Bq * Kq];      // double-buffered [wx(128)|h(512)]
__device__ __align__(16) float g_C[Bq * Hq];         // cell state
__device__ unsigned g_bar_count;
__device__ volatile unsigned g_bar_gen;

__device__ __forceinline__ float tanh_approx(float x) {
    float y;
    asm("tanh.approx.f32 %0, %1;" : "=f"(y) : "f"(x));
    return y;
}
__device__ __forceinline__ uint32_t tf32r(float f) {
    uint32_t u;
    asm("cvt.rna.tf32.f32 %0, %1;" : "=r"(u) : "f"(f));
    return u;
}

#define MMA_TF32(c, a0, a1, a2, a3, b0, b1)                              \
    asm volatile(                                                        \
        "mma.sync.aligned.m16n8k8.row.col.f32.tf32.tf32.f32 "            \
        "{%0,%1,%2,%3},{%4,%5,%6,%7},{%8,%9},{%0,%1,%2,%3};"             \
        : "+f"((c)[0]), "+f"((c)[1]), "+f"((c)[2]), "+f"((c)[3])         \
        : "r"(a0), "r"(a1), "r"(a2), "r"(a3), "r"(b0), "r"(b1))

__device__ __forceinline__ void grid_bar() {
    __syncthreads();
    if (threadIdx.x == 0) {
        __threadfence();
        unsigned gen = g_bar_gen;
        unsigned old = atomicInc(&g_bar_count, NBLK - 1);
        if (old == NBLK - 1) {
            g_bar_gen = gen + 1;
        } else {
            while (g_bar_gen == gen) __nanosleep(64);
        }
        __threadfence();
    }
    __syncthreads();
}

// ---------------- prep: split weights, bias, zero state ----------------
__global__ __launch_bounds__(256) void prep_weights(const float* __restrict__ Wih,
                                                    const float* __restrict__ Whh,
                                                    const float* __restrict__ bih,
                                                    const float* __restrict__ bhh) {
    int i = blockIdx.x * blockDim.x + threadIdx.x;
    int stride = gridDim.x * blockDim.x;
    for (int idx = i; idx < Gq * Kq; idx += stride) {
        int jp = idx / Kq, k = idx - jp * Kq;
        int h = jp >> 2, g = jp & 3;
        int j = g * Hq + h;  // torch gate order i,f,g,o
        float v = (k < Nq) ? Wih[j * Nq + k] : Whh[j * Hq + (k - Nq)];
        float hi = __uint_as_float(tf32r(v));
        float lo = __uint_as_float(tf32r(v - hi));
        g_Wh[idx] = hi;
        g_Wl[idx] = lo;
    }
    for (int idx = i; idx < Gq; idx += stride) {
        int h = idx >> 2, g = idx & 3;
        int j = g * Hq + h;
        g_bias[idx] = bih[j] + bhh[j];
    }
    for (int idx = i; idx < Bq * Kq; idx += stride) {
        g_A[0][idx] = 0.f;
        g_A[1][idx] = 0.f;
    }
    for (int idx = i; idx < Bq * Hq; idx += stride) g_C[idx] = 0.f;
}

// ---------------- prep: z2[b,n,s] = sum_t dx[b,t,n]*W_a2[s,t] + b_a2[s] ----------------
__global__ __launch_bounds__(256) void prep_z2(const float* __restrict__ dx,
                                               const float* __restrict__ Wa2,
                                               const float* __restrict__ ba2) {
    __shared__ float sdx[Tq * Nq];
    int b = blockIdx.x, tid = threadIdx.x;
    const float* dxb = dx + b * Tq * Nq;
    for (int i = tid; i < Tq * Nq; i += 256) sdx[i] = dxb[i];
    __syncthreads();
    for (int o = tid; o < Nq * Tq; o += 256) {
        int s = o & 63, n = o >> 6;
        float acc = 0.f;
#pragma unroll 8
        for (int t = 0; t < Tq; t++) acc += sdx[t * Nq + n] * __ldg(&Wa2[s * Tq + t]);
        g_z2[(b * Nq + n) * Tq + s] = acc + ba2[s];
    }
}

// ---------------- persistent main kernel: 64 steps, 2 phases per step ----------------
__global__ __launch_bounds__(NTHR) void main_kernel(const float* __restrict__ Wa1,
                                                    const float* __restrict__ ba1,
                                                    const float* __restrict__ Wa3,
                                                    const float* __restrict__ ba3,
                                                    const float* __restrict__ dx,
                                                    float* __restrict__ out) {
    __shared__ float sAh[64 * 36], sAl[64 * 36];
    __shared__ float sWh[64 * 36], sWl[64 * 36];
    __shared__ float hs[2][1024];
    __shared__ float z1s[2][64];
    __shared__ float wa3s[64];
    __shared__ float red[2][4];

    const int cta = blockIdx.x, tid = threadIdx.x;
    // phase A ids
    const int pa_b2 = tid >> 7;           // batch-in-pair for z1
    const int pa_s = (tid >> 1) & 63;     // attention s index
    const int pa_part = tid & 1;          // half of 1024-dot
    const int b0 = cta * 2;
    // phase B ids
    const int cm = cta >> 5, cn = cta & 31;
    const int bm = cm * 64, jb = cn * 64;
    const int wid = tid >> 5, lane = tid & 31;
    const int wm = (wid >> 2) * 32, wn = (wid & 3) * 16;
    const int gid = lane >> 2, tig = lane & 3;

    if (tid < 64) wa3s[tid] = Wa3[tid];
    const float ba3v = ba3[0];
    const float ba1v = ba1[pa_s];

    for (int t = 0; t < Tq; t++) {
        const int rb = t & 1;
        const float* Ar = g_A[rb];
        float* Arw = g_A[rb];       // wx writes (phase A)
        float* Aw = g_A[rb ^ 1];    // h writes (phase B)

        // ================= phase A: z1 + attention =================
        for (int i = tid; i < 256; i += NTHR) {
            int bb = i >> 7, k4 = (i & 127) * 4;
            *(float4*)&hs[bb][k4] = *(const float4*)(Ar + (b0 + bb) * Kq + Nq + k4);
            *(float4*)&hs[bb][512 + k4] = *(const float4*)(g_C + (b0 + bb) * Hq + k4);
        }
        __syncthreads();
        {
            const float* wr = Wa1 + pa_s * 1024 + pa_part * 512;
            const float* hp = hs[pa_b2] + pa_part * 512;
            float a0 = 0.f, a1 = 0.f, a2 = 0.f, a3 = 0.f;
#pragma unroll 8
            for (int k = 0; k < 512; k += 4) {
                float4 w = *(const float4*)(wr + k);
                a0 += hp[k] * w.x;
                a1 += hp[k + 1] * w.y;
                a2 += hp[k + 2] * w.z;
                a3 += hp[k + 3] * w.w;
            }
            float acc = (a0 + a1) + (a2 + a3);
            acc += __shfl_xor_sync(0xffffffffu, acc, 1);
            if (pa_part == 0) z1s[pa_b2][pa_s] = acc + ba1v;
        }
        __syncthreads();
        {
            int bb = tid >> 7, n = tid & 127;
            int b = b0 + bb;
            const float4* z2r = (const float4*)(g_z2 + (b * Nq + n) * Tq);
            float e = ba3v;
#pragma unroll
            for (int s4 = 0; s4 < Tq / 4; s4++) {
                float4 z = z2r[s4];
                int s = s4 * 4;
                e += tanh_approx(z1s[bb][s + 0] + z.x) * wa3s[s + 0];
                e += tanh_approx(z1s[bb][s + 1] + z.y) * wa3s[s + 1];
                e += tanh_approx(z1s[bb][s + 2] + z.z) * wa3s[s + 2];
                e += tanh_approx(z1s[bb][s + 3] + z.w) * wa3s[s + 3];
            }
            float m = e;
            for (int o = 16; o > 0; o >>= 1) m = fmaxf(m, __shfl_xor_sync(0xffffffffu, m, o));
            if (lane == 0) red[bb][wid & 3] = m;
            __syncthreads();
            m = fmaxf(fmaxf(red[bb][0], red[bb][1]), fmaxf(red[bb][2], red[bb][3]));
            float p = __expf(e - m);
            float sum = p;
            for (int o = 16; o > 0; o >>= 1) sum += __shfl_xor_sync(0xffffffffu, sum, o);
            __syncthreads();
            if (lane == 0) red[bb][wid & 3] = sum;
            __syncthreads();
            sum = red[bb][0] + red[bb][1] + red[bb][2] + red[bb][3];
            float w = p / sum;
            Arw[b * Kq + n] = w * dx[(b * Tq + t) * Nq + n];
        }
        grid_bar();

        // ================= phase B: 3xTF32 GEMM + fused LSTM =================
        float cacc[2][2][4] = {};
        float4 ra[2], rwh[2], rwl[2];
#pragma unroll
        for (int l = 0; l < 2; l++) {
            int idx = tid + l * 256;
            int row = idx >> 3, k4 = idx & 7;
            ra[l] = *(const float4*)(Ar + (bm + row) * Kq + k4 * 4);
            rwh[l] = *(const float4*)(g_Wh + (jb + row) * Kq + k4 * 4);
            rwl[l] = *(const float4*)(g_Wl + (jb + row) * Kq + k4 * 4);
        }
        for (int ch = 0; ch < 20; ch++) {
#pragma unroll
            for (int l = 0; l < 2; l++) {
                int idx = tid + l * 256;
                int row = idx >> 3, k4 = idx & 7;
                uint32_t* ah = (uint32_t*)(sAh + row * 36 + k4 * 4);
                uint32_t* al = (uint32_t*)(sAl + row * 36 + k4 * 4);
                uint32_t h0 = tf32r(ra[l].x), h1 = tf32r(ra[l].y);
                uint32_t h2 = tf32r(ra[l].z), h3 = tf32r(ra[l].w);
                ah[0] = h0; ah[1] = h1; ah[2] = h2; ah[3] = h3;
                al[0] = tf32r(ra[l].x - __uint_as_float(h0));
                al[1] = tf32r(ra[l].y - __uint_as_float(h1));
                al[2] = tf32r(ra[l].z - __uint_as_float(h2));
                al[3] = tf32r(ra[l].w - __uint_as_float(h3));
                *(float4*)(sWh + row * 36 + k4 * 4) = rwh[l];
                *(float4*)(sWl + row * 36 + k4 * 4) = rwl[l];
            }
            __syncthreads();
            if (ch < 19) {
                int k0 = (ch + 1) * 32;
#pragma unroll
                for (int l = 0; l < 2; l++) {
                    int idx = tid + l * 256;
                    int row = idx >> 3, k4 = idx & 7;
                    ra[l] = *(const float4*)(Ar + (bm + row) * Kq + k0 + k4 * 4);
                    rwh[l] = *(const float4*)(g_Wh + (jb + row) * Kq + k0 + k4 * 4);
                    rwl[l] = *(const float4*)(g_Wl + (jb + row) * Kq + k0 + k4 * 4);
                }
            }
            const uint32_t* Ah = (const uint32_t*)sAh;
            const uint32_t* Al = (const uint32_t*)sAl;
            const uint32_t* Wh = (const uint32_t*)sWh;
            const uint32_t* Wl = (const uint32_t*)sWl;
#pragma unroll
            for (int k8 = 0; k8 < 4; k8++) {
                int cb = k8 * 8 + tig;
                uint32_t afh[2][4], afl[2][4];
#pragma unroll
                for (int mt = 0; mt < 2; mt++) {
                    int r0 = (wm + mt * 16 + gid) * 36;
                    afh[mt][0] = Ah[r0 + cb];
                    afh[mt][1] = Ah[r0 + 8 * 36 + cb];
                    afh[mt][2] = Ah[r0 + cb + 4];
                    afh[mt][3] = Ah[r0 + 8 * 36 + cb + 4];
                    afl[mt][0] = Al[r0 + cb];
                    afl[mt][1] = Al[r0 + 8 * 36 + cb];
                    afl[mt][2] = Al[r0 + cb + 4];
                    afl[mt][3] = Al[r0 + 8 * 36 + cb + 4];
                }
#pragma unroll
                for (int nt = 0; nt < 2; nt++) {
                    int nr = (wn + nt * 8 + gid) * 36;
                    uint32_t bh0 = Wh[nr + cb], bh1 = Wh[nr + cb + 4];
                    uint32_t bl0 = Wl[nr + cb], bl1 = Wl[nr + cb + 4];
#pragma unroll
                    for (int mt = 0; mt < 2; mt++) {
                        MMA_TF32(cacc[mt][nt], afh[mt][0], afh[mt][1], afh[mt][2], afh[mt][3], bh0, bh1);
                        MMA_TF32(cacc[mt][nt], afh[mt][0], afh[mt][1], afh[mt][2], afh[mt][3], bl0, bl1);
                        MMA_TF32(cacc[mt][nt], afl[mt][0], afl[mt][1], afl[mt][2], afl[mt][3], bh0, bh1);
                    }
                }
            }
            __syncthreads();
        }
        // fused LSTM epilogue: pair threads (tig even gets partner's 2 cols -> 4 gates)
#pragma unroll
        for (int mt = 0; mt < 2; mt++) {
#pragma unroll
            for (int nt = 0; nt < 2; nt++) {
                float v0 = cacc[mt][nt][0], v1 = cacc[mt][nt][1];
                float v2 = cacc[mt][nt][2], v3 = cacc[mt][nt][3];
                float p0 = __shfl_xor_sync(0xffffffffu, v0, 1);
                float p1 = __shfl_xor_sync(0xffffffffu, v1, 1);
                float p2 = __shfl_xor_sync(0xffffffffu, v2, 1);
                float p3 = __shfl_xor_sync(0xffffffffu, v3, 1);
                if ((tig & 1) == 0) {
                    int jcol = jb + wn + nt * 8 + 2 * tig;  // multiple of 4
                    int h = jcol >> 2;
                    float4 bias = *(const float4*)(g_bias + jcol);
                    int b = bm + wm + mt * 16 + gid;
#pragma unroll
                    for (int rr = 0; rr < 2; rr++) {
                        int bb = b + rr * 8;
                        float gi = (rr ? v2 : v0) + bias.x;
                        float gf = (rr ? v3 : v1) + bias.y;
                        float gg = (rr ? p2 : p0) + bias.z;
                        float go = (rr ? p3 : p1) + bias.w;
                        float co = g_C[bb * Hq + h];
                        float si = 1.f / (1.f + __expf(-gi));
                        float sf = 1.f / (1.f + __expf(-gf));
                        float so = 1.f / (1.f + __expf(-go));
                        float cn2 = sf * co + si * tanhf(gg);
                        float hn = so * tanhf(cn2);
                        g_C[bb * Hq + h] = cn2;
                        Aw[bb * Kq + Nq + h] = hn;
                        out[(bb * Tq + t) * Hq + h] = hn;
                    }
                }
            }
        }
        grid_bar();
    }
}

extern "C" void kernel_launch(void* const* d_in, const int* in_sizes, int n_in,
                              void* d_out, int out_size) {
    const float* dx  = (const float*)d_in[0];
    const float* Wa1 = (const float*)d_in[1];
    const float* ba1 = (const float*)d_in[2];
    const float* Wa2 = (const float*)d_in[3];
    const float* ba2 = (const float*)d_in[4];
    const float* Wa3 = (const float*)d_in[5];
    const float* ba3 = (const float*)d_in[6];
    const float* Wih = (const float*)d_in[7];
    const float* Whh = (const float*)d_in[8];
    const float* bih = (const float*)d_in[9];
    const float* bhh = (const float*)d_in[10];
    float* out = (float*)d_out;

    prep_weights<<<512, 256>>>(Wih, Whh, bih, bhh);
    prep_z2<<<Bq, 256>>>(dx, Wa2, ba2);
    main_kernel<<<NBLK, NTHR>>>(Wa1, ba1, Wa3, ba3, dx, out);
}